// round 11
// baseline (speedup 1.0000x reference)
#include <cuda_runtime.h>
#include <cuda_fp16.h>

// Problem constants
#define Bz   2
#define Hh   160
#define Ww   160
#define SPAN 11
#define KK   23              // 2*SPAN+1
#define PH   (Hh + 2*SPAN)   // 182
#define PW   (Ww + 2*SPAN)   // 182
#define PPW  96              // pairs per padded row (padded from 91)
#define NPIX (Bz*Hh*Ww)      // 51200
#define HW   (Hh*Ww)

#define NBLK 148
#define NTHR 512
#define NWARPS (NBLK*(NTHR/32))   // 2368

// s = sqrt(0.5*log2(e)); neighbor scaled by 10*s, center by s -> exp2 arg = -ss
#define SSC  0.8493218f
#define C1   (-0.72134752f)  // -0.5*log2(e)

// pair-staging tasks: 2 parities x Bz x 160 rows x m in [5,85]
#define NTASK (2*Bz*Hh*81)   // 51840

// __device__ globals: zero-init at load; pad entries never written (stay 0 =>
// sy=0 => zero contribution); mutable state self-resets per launch.
// Interleaved records: g_PK[2*rec] = {r2,g2,b2,src2}, g_PK[2*rec+1] = {sy0,sy1,sy2,0}
__device__ uint4  g_PK[2*2*Bz*PH*PPW];
__device__ float4 g_crgb[NPIX];       // center rgb * SSC (fp32)
__device__ float4 g_cw[NPIX];         // center softmax {y0,y1,y2,0}
__device__ int    g_list[NPIX];
__device__ int    g_count;
__device__ unsigned g_bar1, g_done;
__device__ double g_ce, g_gcrf;

__device__ __forceinline__ float ex2f(float x) {
    float y; asm("ex2.approx.f32 %0, %1;" : "=f"(y) : "f"(x)); return y;
}
__device__ __forceinline__ unsigned h2u(__half2 h) { return *reinterpret_cast<unsigned*>(&h); }
__device__ __forceinline__ __half2 u2h(unsigned u) { return *reinterpret_cast<__half2*>(&u); }
__device__ __forceinline__ __half2 hex2(__half2 x) {
    unsigned xi = h2u(x), yo;
    asm("ex2.approx.f16x2 %0, %1;" : "=r"(yo) : "r"(xi));
    return u2h(yo);
}
__device__ __forceinline__ __half2 h2and(__half2 a, unsigned m) {
    unsigned u = h2u(a) & m; return u2h(u);
}

// softmax + channel values for one padded column (zeros if pad column)
__device__ __forceinline__ void loadcol(
    const float* __restrict__ logit, const float* __restrict__ image,
    const float* __restrict__ srcmap, int b, int prow, int pcol, float* v)
{
    if (pcol < SPAN || pcol >= SPAN + Ww) {
        #pragma unroll
        for (int k = 0; k < 7; k++) v[k] = 0.f;
        return;
    }
    int i  = prow - SPAN, jj = pcol - SPAN;
    int hw = i * Ww + jj;
    const float* lg = logit + (size_t)b * 3 * HW + hw;
    float l0 = lg[0], l1 = lg[HW], l2 = lg[2*HW];
    float m  = fmaxf(l0, fmaxf(l1, l2));
    float e0 = expf(l0 - m), e1 = expf(l1 - m), e2 = expf(l2 - m);
    float inv = 1.f / (e0 + e1 + e2);
    float src = srcmap[b * HW + hw];
    const float* im = image + (size_t)b * 3 * HW + hw;
    v[0] = 10.f*SSC*im[0]; v[1] = 10.f*SSC*im[HW]; v[2] = 10.f*SSC*im[2*HW];
    v[3] = src;
    v[4] = src * e0 * inv; v[5] = src * e1 * inv; v[6] = src * e2 * inv;
}

__global__ void __launch_bounds__(NTHR, 1) fused_kernel(
    const float* __restrict__ logit, const int* __restrict__ target,
    const float* __restrict__ image, const float* __restrict__ srcmap,
    const float* __restrict__ dstmap, float* __restrict__ out)
{
    __shared__ float    red[NTHR/32];
    __shared__ unsigned s_fi[NTHR/32][KK+1];  // half2 {fi,fi} per di
    __shared__ unsigned s_fj[NTHR/32][12];    // {fj(2q), fj(2q+1)} per q
    const int tid  = threadIdx.x;
    const int lane = tid & 31;
    const int wid  = tid >> 5;

    // ============ Phase 1a: per-pixel softmax, CE, centers, compaction ======
    {
        int t = blockIdx.x * NTHR + tid;
        float ce = 0.f;
        bool active = false;

        if (t < NPIX) {
            int b  = t / HW;
            int hw = t - b * HW;

            const float* lg = logit + (size_t)b * 3 * HW + hw;
            float l0 = lg[0], l1 = lg[HW], l2 = lg[2*HW];
            float m  = fmaxf(l0, fmaxf(l1, l2));
            float e0 = expf(l0 - m), e1 = expf(l1 - m), e2 = expf(l2 - m);
            float s  = e0 + e1 + e2;
            float inv = 1.f / s;

            int   tg  = target[t];
            float lt  = (tg == 0) ? l0 : ((tg == 1) ? l1 : l2);
            float dst = dstmap[t];
            ce = -((lt - m) - logf(s)) * dst;

            const float* im = image + (size_t)b * 3 * HW + hw;
            g_crgb[t] = make_float4(SSC*im[0], SSC*im[HW], SSC*im[2*HW], 0.f);
            g_cw[t]   = make_float4(e0*inv, e1*inv, e2*inv, 0.f);

            active = (dst == 0.0f);
        }

        unsigned mask = __ballot_sync(0xffffffffu, active);
        if (mask) {
            int leader = __ffs(mask) - 1;
            int base   = 0;
            if (lane == leader) base = atomicAdd(&g_count, __popc(mask));
            base = __shfl_sync(0xffffffffu, base, leader);
            if (active) g_list[base + __popc(mask & ((1u << lane) - 1))] = t;
        }

        #pragma unroll
        for (int s2 = 16; s2 > 0; s2 >>= 1)
            ce += __shfl_xor_sync(0xffffffffu, ce, s2);
        if (lane == 0) red[wid] = ce;
        __syncthreads();
        if (wid == 0) {
            float v = (lane < NTHR/32) ? red[lane] : 0.f;
            #pragma unroll
            for (int s2 = 8; s2 > 0; s2 >>= 1)
                v += __shfl_xor_sync(0xffffffffu, v, s2);
            if (lane == 0) atomicAdd(&g_ce, (double)v);
        }
    }

    // ============ Phase 1b: channel-paired staging (both parity copies) =====
    {
        int tt = blockIdx.x * NTHR + tid;
        if (tt < NTASK) {
            int m   = tt % 81 + 5;        // pair index 5..85
            int r2  = tt / 81;
            int row = r2 % Hh + SPAN;     // padded row 11..170
            int r3  = r2 / Hh;            // 0..3
            int b   = r3 & 1;
            int p   = r3 >> 1;            // parity copy
            int c0  = 2*m + p;            // padded cols (c0, c0+1)

            float A[7], B[7];
            loadcol(logit, image, srcmap, b, row, c0,     A);
            loadcol(logit, image, srcmap, b, row, c0 + 1, B);

            uint4 o1, o2;
            o1.x = h2u(__floats2half2_rn(A[0], B[0]));   // r pair
            o1.y = h2u(__floats2half2_rn(A[1], B[1]));   // g pair
            o1.z = h2u(__floats2half2_rn(A[2], B[2]));   // b pair
            o1.w = h2u(__floats2half2_rn(A[3], B[3]));   // src pair
            o2.x = h2u(__floats2half2_rn(A[4], B[4]));   // sy0 pair
            o2.y = h2u(__floats2half2_rn(A[5], B[5]));   // sy1 pair
            o2.z = h2u(__floats2half2_rn(A[6], B[6]));   // sy2 pair
            o2.w = 0u;
            int rec = ((p * Bz + b) * PH + row) * PPW + m;
            g_PK[2*rec]     = o1;         // same 128B line as o2
            g_PK[2*rec + 1] = o2;
        }
    }

    // ================= Grid barrier =========================================
    __syncthreads();
    if (tid == 0) {
        __threadfence();
        atomicAdd(&g_bar1, 1u);
        while (*(volatile unsigned*)&g_bar1 < NBLK) { __nanosleep(32); }
        __threadfence();
    }
    __syncthreads();

    // ========== Phase 2: warp-per-pixel, 2 offsets/lane, half2 math =========
    {
        const int count = *(volatile int*)&g_count;
        const int gw    = blockIdx.x * (NTHR/32) + wid;
        float facc = 0.f;

        // pixel-invariant per-lane descriptors (hoisted out of the px loop)
        int      pidx[9];    // record index di*PPW+q
        unsigned pmsk[9];    // lane-pair validity mask
        int      pdq[9];     // di | (q<<5)  (for fifj build)
        #pragma unroll
        for (int it = 0; it < 9; it++) {
            int s = it*32 + lane;
            bool valid = (s < 276);               // 23 rows x 12 pairs
            int sc = valid ? s : 0;
            int di = (sc * 2731) >> 15;           // sc/12
            int q  = sc - di * 12;
            pidx[it] = di * PPW + q;
            pmsk[it] = valid ? ((q == 11) ? 0x0000FFFFu : 0xFFFFFFFFu) : 0u;
            pdq[it]  = di | (q << 5);
        }

        for (int px = gw; px < count; px += NWARPS) {
            int t  = g_list[px];
            int b  = t / HW;
            int hw = t - b * HW;
            int i  = hw / Ww;
            int j  = hw - i * Ww;

            // per-pixel spatial tables (warp-cooperative fp32 MUFU)
            if (lane < KK) {
                float xi = (float)(5*i - lane + SPAN) * (1.f/6.f);
                s_fi[wid][lane] = h2u(__float2half2_rn(ex2f(xi*xi*C1)));
            }
            if (lane < 12) {
                int djA = 2*lane;
                float xa = (float)(5*j - djA     + SPAN) * (1.f/6.f);
                float xb = (float)(5*j - djA - 1 + SPAN) * (1.f/6.f);
                s_fj[wid][lane] = h2u(__floats2half2_rn(ex2f(xa*xa*C1), ex2f(xb*xb*C1)));
            }
            __syncwarp();

            // fold spatial product per lane-slot: fifj = fi[di]*fj[q]
            __half2 fifj[9];
            #pragma unroll
            for (int it = 0; it < 9; it++) {
                int di = pdq[it] & 31, q = pdq[it] >> 5;
                fifj[it] = __hmul2(u2h(s_fi[wid][di]), u2h(s_fj[wid][q]));
            }
            __syncwarp();      // tables free for next pixel after this point

            float4 cr = g_crgb[t];
            float4 cy = g_cw[t];
            __half2 crr = __float2half2_rn(cr.x);
            __half2 cgg = __float2half2_rn(cr.y);
            __half2 cbb = __float2half2_rn(cr.z);
            __half2 w0  = __float2half2_rn(1.f - cy.x);
            __half2 w1  = __float2half2_rn(1.f - cy.y);
            __half2 w2  = __float2half2_rn(1.f - cy.z);
            const uint4* PK = g_PK
                + 2*((((j & 1) * Bz + b) * PH + i) * PPW + (j >> 1));

            __half2 acc2 = u2h(0u);
            #pragma unroll
            for (int it = 0; it < 9; it++) {
                const uint4* p = PK + 2*pidx[it];
                uint4 v1 = __ldg(p);          // {r,g,b,src} pairs
                uint4 v2 = __ldg(p + 1);      // {sy0,sy1,sy2,0} (same L2 line)
                __half2 dr = __hsub2(crr, u2h(v1.x));
                __half2 dg = __hsub2(cgg, u2h(v1.y));
                __half2 db = __hsub2(cbb, u2h(v1.z));
                __half2 ss = __hfma2(dr, dr, __hfma2(dg, dg, __hmul2(db, db)));
                __half2 krgb = hex2(__hneg2(ss));       // exp(-0.5*||d||^2) x2
                __half2 km = h2and(__hadd2(krgb, fifj[it]), pmsk[it]);
                __half2 sn = __hmul2(u2h(v2.x), w0);    // sum_c sy_c*(1-y_pc)
                sn = __hfma2(u2h(v2.y), w1, sn);
                sn = __hfma2(u2h(v2.z), w2, sn);
                acc2 = __hfma2(km, sn, acc2);
            }
            float2 fa = __half22float2(acc2);
            facc += fa.x + fa.y;
        }

        #pragma unroll
        for (int s2 = 16; s2 > 0; s2 >>= 1)
            facc += __shfl_xor_sync(0xffffffffu, facc, s2);
        __syncthreads();
        if (lane == 0) red[wid] = facc;
        __syncthreads();
        if (wid == 0) {
            float v = (lane < NTHR/32) ? red[lane] : 0.f;
            #pragma unroll
            for (int s2 = 8; s2 > 0; s2 >>= 1)
                v += __shfl_xor_sync(0xffffffffu, v, s2);
            if (lane == 0) atomicAdd(&g_gcrf, (double)v);
        }
    }

    // ================= Fin: last block writes + resets ======================
    __syncthreads();
    if (tid == 0) {
        __threadfence();
        unsigned d = atomicAdd(&g_done, 1u);
        if (d == NBLK - 1) {
            __threadfence();
            out[0] = (float)((g_ce + 0.15 * g_gcrf) / (double)NPIX);
            g_ce = 0.0; g_gcrf = 0.0;
            g_count = 0; g_bar1 = 0; g_done = 0;
        }
    }
}

extern "C" void kernel_launch(void* const* d_in, const int* in_sizes, int n_in,
                              void* d_out, int out_size)
{
    const float* logit  = (const float*)d_in[0];
    const int*   target = (const int*)  d_in[1];
    const float* image  = (const float*)d_in[2];
    const float* srcmap = (const float*)d_in[3];
    const float* dstmap = (const float*)d_in[4];
    float* out = (float*)d_out;

    fused_kernel<<<NBLK, NTHR>>>(logit, target, image, srcmap, dstmap, out);
}

// round 16
// speedup vs baseline: 1.1620x; 1.1620x over previous
#include <cuda_runtime.h>
#include <cuda_fp16.h>

// Problem constants
#define Bz   2
#define Hh   160
#define Ww   160
#define SPAN 11
#define KK   23              // 2*SPAN+1
#define PH   (Hh + 2*SPAN)   // 182
#define PW   (Ww + 2*SPAN)   // 182
#define PPW  96              // pairs per padded row (padded from 91)
#define NPIX (Bz*Hh*Ww)      // 51200
#define HW   (Hh*Ww)

#define NBLK 148
#define NTHR 512
#define NWARPS (NBLK*(NTHR/32))   // 2368

// s = sqrt(0.5*log2(e)); neighbor scaled by 10*s, center by s -> exp2 arg = -ss
#define SSC  0.8493218f
#define C1   (-0.72134752f)  // -0.5*log2(e)

// pair-staging tasks: 2 parities x Bz x 160 rows x m in [5,85]
#define NTASK (2*Bz*Hh*81)   // 51840

// __device__ globals: zero-init at load; pad entries never written (stay 0 =>
// sy=0 => zero contribution); mutable state self-resets per launch.
// Dense separate arrays; src dropped (dead in phase 2): 24 B per offset-pair.
__device__ uint4  g_P1[2*Bz*PH*PPW];  // {r2, g2, b2, sy0_2} half2 x4 per pair
__device__ uint2  g_P2[2*Bz*PH*PPW];  // {sy1_2, sy2_2}
__device__ float4 g_crgb[NPIX];       // center rgb * SSC (fp32)
__device__ float4 g_cw[NPIX];         // center softmax {y0,y1,y2,0}
__device__ int    g_list[NPIX];
__device__ int    g_count;
__device__ unsigned g_bar1, g_done;
__device__ double g_ce, g_gcrf;

__device__ __forceinline__ float ex2f(float x) {
    float y; asm("ex2.approx.f32 %0, %1;" : "=f"(y) : "f"(x)); return y;
}
__device__ __forceinline__ unsigned h2u(__half2 h) { return *reinterpret_cast<unsigned*>(&h); }
__device__ __forceinline__ __half2 u2h(unsigned u) { return *reinterpret_cast<__half2*>(&u); }
__device__ __forceinline__ __half2 hex2(__half2 x) {
    unsigned xi = h2u(x), yo;
    asm("ex2.approx.f16x2 %0, %1;" : "=r"(yo) : "r"(xi));
    return u2h(yo);
}
__device__ __forceinline__ __half2 h2and(__half2 a, unsigned m) {
    unsigned u = h2u(a) & m; return u2h(u);
}

// softmax + channel values for one padded column (zeros if pad column)
// v = {10s*r, 10s*g, 10s*b, src*y0, src*y1, src*y2}
__device__ __forceinline__ void loadcol(
    const float* __restrict__ logit, const float* __restrict__ image,
    const float* __restrict__ srcmap, int b, int prow, int pcol, float* v)
{
    if (pcol < SPAN || pcol >= SPAN + Ww) {
        #pragma unroll
        for (int k = 0; k < 6; k++) v[k] = 0.f;
        return;
    }
    int i  = prow - SPAN, jj = pcol - SPAN;
    int hw = i * Ww + jj;
    const float* lg = logit + (size_t)b * 3 * HW + hw;
    float l0 = lg[0], l1 = lg[HW], l2 = lg[2*HW];
    float m  = fmaxf(l0, fmaxf(l1, l2));
    float e0 = expf(l0 - m), e1 = expf(l1 - m), e2 = expf(l2 - m);
    float inv = 1.f / (e0 + e1 + e2);
    float src = srcmap[b * HW + hw];
    const float* im = image + (size_t)b * 3 * HW + hw;
    v[0] = 10.f*SSC*im[0]; v[1] = 10.f*SSC*im[HW]; v[2] = 10.f*SSC*im[2*HW];
    v[3] = src * e0 * inv; v[4] = src * e1 * inv; v[5] = src * e2 * inv;
}

__global__ void __launch_bounds__(NTHR, 1) fused_kernel(
    const float* __restrict__ logit, const int* __restrict__ target,
    const float* __restrict__ image, const float* __restrict__ srcmap,
    const float* __restrict__ dstmap, float* __restrict__ out)
{
    __shared__ float    red[NTHR/32];
    __shared__ unsigned s_fi[NTHR/32][KK+1];  // half2 {fi,fi} per di
    __shared__ unsigned s_fj[NTHR/32][12];    // {fj(2q), fj(2q+1)} per q
    const int tid  = threadIdx.x;
    const int lane = tid & 31;
    const int wid  = tid >> 5;

    // ============ Phase 1a: per-pixel softmax, CE, centers, compaction ======
    {
        int t = blockIdx.x * NTHR + tid;
        float ce = 0.f;
        bool active = false;

        if (t < NPIX) {
            int b  = t / HW;
            int hw = t - b * HW;

            const float* lg = logit + (size_t)b * 3 * HW + hw;
            float l0 = lg[0], l1 = lg[HW], l2 = lg[2*HW];
            float m  = fmaxf(l0, fmaxf(l1, l2));
            float e0 = expf(l0 - m), e1 = expf(l1 - m), e2 = expf(l2 - m);
            float s  = e0 + e1 + e2;
            float inv = 1.f / s;

            int   tg  = target[t];
            float lt  = (tg == 0) ? l0 : ((tg == 1) ? l1 : l2);
            float dst = dstmap[t];
            ce = -((lt - m) - logf(s)) * dst;

            const float* im = image + (size_t)b * 3 * HW + hw;
            g_crgb[t] = make_float4(SSC*im[0], SSC*im[HW], SSC*im[2*HW], 0.f);
            g_cw[t]   = make_float4(e0*inv, e1*inv, e2*inv, 0.f);

            active = (dst == 0.0f);
        }

        unsigned mask = __ballot_sync(0xffffffffu, active);
        if (mask) {
            int leader = __ffs(mask) - 1;
            int base   = 0;
            if (lane == leader) base = atomicAdd(&g_count, __popc(mask));
            base = __shfl_sync(0xffffffffu, base, leader);
            if (active) g_list[base + __popc(mask & ((1u << lane) - 1))] = t;
        }

        #pragma unroll
        for (int s2 = 16; s2 > 0; s2 >>= 1)
            ce += __shfl_xor_sync(0xffffffffu, ce, s2);
        if (lane == 0) red[wid] = ce;
        __syncthreads();
        if (wid == 0) {
            float v = (lane < NTHR/32) ? red[lane] : 0.f;
            #pragma unroll
            for (int s2 = 8; s2 > 0; s2 >>= 1)
                v += __shfl_xor_sync(0xffffffffu, v, s2);
            if (lane == 0) atomicAdd(&g_ce, (double)v);
        }
    }

    // ============ Phase 1b: channel-paired staging (both parity copies) =====
    {
        int tt = blockIdx.x * NTHR + tid;
        if (tt < NTASK) {
            int m   = tt % 81 + 5;        // pair index 5..85
            int r2  = tt / 81;
            int row = r2 % Hh + SPAN;     // padded row 11..170
            int r3  = r2 / Hh;            // 0..3
            int b   = r3 & 1;
            int p   = r3 >> 1;            // parity copy
            int c0  = 2*m + p;            // padded cols (c0, c0+1)

            float A[6], B[6];
            loadcol(logit, image, srcmap, b, row, c0,     A);
            loadcol(logit, image, srcmap, b, row, c0 + 1, B);

            uint4 o1; uint2 o2;
            o1.x = h2u(__floats2half2_rn(A[0], B[0]));   // r pair
            o1.y = h2u(__floats2half2_rn(A[1], B[1]));   // g pair
            o1.z = h2u(__floats2half2_rn(A[2], B[2]));   // b pair
            o1.w = h2u(__floats2half2_rn(A[3], B[3]));   // sy0 pair
            o2.x = h2u(__floats2half2_rn(A[4], B[4]));   // sy1 pair
            o2.y = h2u(__floats2half2_rn(A[5], B[5]));   // sy2 pair
            int idx = ((p * Bz + b) * PH + row) * PPW + m;
            g_P1[idx] = o1;
            g_P2[idx] = o2;
        }
    }

    // ================= Grid barrier =========================================
    __syncthreads();
    if (tid == 0) {
        __threadfence();
        atomicAdd(&g_bar1, 1u);
        while (*(volatile unsigned*)&g_bar1 < NBLK) { __nanosleep(32); }
        __threadfence();
    }
    __syncthreads();

    // ========== Phase 2: warp-per-pixel, 2 offsets/lane, half2 math =========
    {
        const int count = *(volatile int*)&g_count;
        const int gw    = blockIdx.x * (NTHR/32) + wid;
        float facc = 0.f;

        // pixel-invariant per-lane descriptors (hoisted out of the px loop)
        int      pidx[9];    // record index di*PPW+q
        unsigned pmsk[9];    // lane-pair validity mask
        int      pdq[9];     // di | (q<<5)  (for fifj build)
        #pragma unroll
        for (int it = 0; it < 9; it++) {
            int s = it*32 + lane;
            bool valid = (s < 276);               // 23 rows x 12 pairs
            int sc = valid ? s : 0;
            int di = (sc * 2731) >> 15;           // sc/12
            int q  = sc - di * 12;
            pidx[it] = di * PPW + q;
            pmsk[it] = valid ? ((q == 11) ? 0x0000FFFFu : 0xFFFFFFFFu) : 0u;
            pdq[it]  = di | (q << 5);
        }

        for (int px = gw; px < count; px += NWARPS) {
            int t  = g_list[px];
            int b  = t / HW;
            int hw = t - b * HW;
            int i  = hw / Ww;
            int j  = hw - i * Ww;

            // per-pixel spatial tables (warp-cooperative fp32 MUFU)
            if (lane < KK) {
                float xi = (float)(5*i - lane + SPAN) * (1.f/6.f);
                s_fi[wid][lane] = h2u(__float2half2_rn(ex2f(xi*xi*C1)));
            }
            if (lane < 12) {
                int djA = 2*lane;
                float xa = (float)(5*j - djA     + SPAN) * (1.f/6.f);
                float xb = (float)(5*j - djA - 1 + SPAN) * (1.f/6.f);
                s_fj[wid][lane] = h2u(__floats2half2_rn(ex2f(xa*xa*C1), ex2f(xb*xb*C1)));
            }
            __syncwarp();

            // fold spatial product per lane-slot: fifj = fi[di]*fj[q]
            __half2 fifj[9];
            #pragma unroll
            for (int it = 0; it < 9; it++) {
                int di = pdq[it] & 31, q = pdq[it] >> 5;
                fifj[it] = __hmul2(u2h(s_fi[wid][di]), u2h(s_fj[wid][q]));
            }
            __syncwarp();      // tables free for next pixel after this point

            float4 cr = g_crgb[t];
            float4 cy = g_cw[t];
            __half2 crr = __float2half2_rn(cr.x);
            __half2 cgg = __float2half2_rn(cr.y);
            __half2 cbb = __float2half2_rn(cr.z);
            __half2 w0  = __float2half2_rn(1.f - cy.x);
            __half2 w1  = __float2half2_rn(1.f - cy.y);
            __half2 w2  = __float2half2_rn(1.f - cy.z);
            int wbase = (((j & 1) * Bz + b) * PH + i) * PPW + (j >> 1);
            const uint4* B1 = g_P1 + wbase;
            const uint2* B2 = g_P2 + wbase;

            __half2 acc2 = u2h(0u);
            #pragma unroll
            for (int it = 0; it < 9; it++) {
                uint4 v1 = __ldg(B1 + pidx[it]);   // {r,g,b,sy0} pairs (16B)
                uint2 v2 = __ldg(B2 + pidx[it]);   // {sy1,sy2} pairs (8B)
                __half2 dr = __hsub2(crr, u2h(v1.x));
                __half2 dg = __hsub2(cgg, u2h(v1.y));
                __half2 db = __hsub2(cbb, u2h(v1.z));
                __half2 ss = __hfma2(dr, dr, __hfma2(dg, dg, __hmul2(db, db)));
                __half2 krgb = hex2(__hneg2(ss));       // exp(-0.5*||d||^2) x2
                __half2 km = h2and(__hadd2(krgb, fifj[it]), pmsk[it]);
                __half2 sn = __hmul2(u2h(v1.w), w0);    // sum_c sy_c*(1-y_pc)
                sn = __hfma2(u2h(v2.x), w1, sn);
                sn = __hfma2(u2h(v2.y), w2, sn);
                acc2 = __hfma2(km, sn, acc2);
            }
            float2 fa = __half22float2(acc2);
            facc += fa.x + fa.y;
        }

        #pragma unroll
        for (int s2 = 16; s2 > 0; s2 >>= 1)
            facc += __shfl_xor_sync(0xffffffffu, facc, s2);
        __syncthreads();
        if (lane == 0) red[wid] = facc;
        __syncthreads();
        if (wid == 0) {
            float v = (lane < NTHR/32) ? red[lane] : 0.f;
            #pragma unroll
            for (int s2 = 8; s2 > 0; s2 >>= 1)
                v += __shfl_xor_sync(0xffffffffu, v, s2);
            if (lane == 0) atomicAdd(&g_gcrf, (double)v);
        }
    }

    // ================= Fin: last block writes + resets ======================
    __syncthreads();
    if (tid == 0) {
        __threadfence();
        unsigned d = atomicAdd(&g_done, 1u);
        if (d == NBLK - 1) {
            __threadfence();
            out[0] = (float)((g_ce + 0.15 * g_gcrf) / (double)NPIX);
            g_ce = 0.0; g_gcrf = 0.0;
            g_count = 0; g_bar1 = 0; g_done = 0;
        }
    }
}

extern "C" void kernel_launch(void* const* d_in, const int* in_sizes, int n_in,
                              void* d_out, int out_size)
{
    const float* logit  = (const float*)d_in[0];
    const int*   target = (const int*)  d_in[1];
    const float* image  = (const float*)d_in[2];
    const float* srcmap = (const float*)d_in[3];
    const float* dstmap = (const float*)d_in[4];
    float* out = (float*)d_out;

    fused_kernel<<<NBLK, NTHR>>>(logit, target, image, srcmap, dstmap, out);
}

// round 17
// speedup vs baseline: 1.3355x; 1.1492x over previous
#include <cuda_runtime.h>
#include <cuda_fp16.h>

// Problem constants
#define Bz   2
#define Hh   160
#define Ww   160
#define SPAN 11
#define KK   23              // 2*SPAN+1
#define PH   (Hh + 2*SPAN)   // 182
#define PW   (Ww + 2*SPAN)   // 182
#define PPW  96              // pairs per padded row (padded from 91)
#define NPIX (Bz*Hh*Ww)      // 51200
#define HW   (Hh*Ww)

#define NBLK 148
#define NTHR 512
#define NWARPS (NBLK*(NTHR/32))   // 2368

// s = sqrt(0.5*log2(e)); neighbor scaled by 10*s, center by s -> exp2 arg = -ss
#define SSC  0.8493218f
#define C1   (-0.72134752f)  // -0.5*log2(e)

// pair-staging tasks: 2 parities x Bz x 160 rows x m in [5,85]
#define NTASK (2*Bz*Hh*81)   // 51840

// __device__ globals: zero-init at load; pad entries never written (stay 0 =>
// sy=0 => zero contribution); mutable state self-resets per launch.
// Dense separate arrays; src dropped (dead in phase 2): 24 B per offset-pair.
__device__ uint4  g_P1[2*Bz*PH*PPW];  // {r2, g2, b2, sy0_2} half2 x4 per pair
__device__ uint2  g_P2[2*Bz*PH*PPW];  // {sy1_2, sy2_2}
__device__ float4 g_crgb[NPIX];       // center rgb * SSC (fp32)
__device__ float4 g_cw[NPIX];         // center softmax {y0,y1,y2,0}
__device__ int    g_list[NPIX];
__device__ int    g_count;
__device__ unsigned g_bar1, g_done;
__device__ double g_ce, g_gcrf;

__device__ __forceinline__ float ex2f(float x) {
    float y; asm("ex2.approx.f32 %0, %1;" : "=f"(y) : "f"(x)); return y;
}
__device__ __forceinline__ unsigned h2u(__half2 h) { return *reinterpret_cast<unsigned*>(&h); }
__device__ __forceinline__ __half2 u2h(unsigned u) { return *reinterpret_cast<__half2*>(&u); }
__device__ __forceinline__ __half2 hex2(__half2 x) {
    unsigned xi = h2u(x), yo;
    asm("ex2.approx.f16x2 %0, %1;" : "=r"(yo) : "r"(xi));
    return u2h(yo);
}
__device__ __forceinline__ __half2 h2and(__half2 a, unsigned m) {
    unsigned u = h2u(a) & m; return u2h(u);
}

// softmax + channel values for one padded column (zeros if pad column)
// v = {10s*r, 10s*g, 10s*b, src*y0, src*y1, src*y2}
__device__ __forceinline__ void loadcol(
    const float* __restrict__ logit, const float* __restrict__ image,
    const float* __restrict__ srcmap, int b, int prow, int pcol, float* v)
{
    if (pcol < SPAN || pcol >= SPAN + Ww) {
        #pragma unroll
        for (int k = 0; k < 6; k++) v[k] = 0.f;
        return;
    }
    int i  = prow - SPAN, jj = pcol - SPAN;
    int hw = i * Ww + jj;
    const float* lg = logit + (size_t)b * 3 * HW + hw;
    float l0 = lg[0], l1 = lg[HW], l2 = lg[2*HW];
    float m  = fmaxf(l0, fmaxf(l1, l2));
    float e0 = expf(l0 - m), e1 = expf(l1 - m), e2 = expf(l2 - m);
    float inv = 1.f / (e0 + e1 + e2);
    float src = srcmap[b * HW + hw];
    const float* im = image + (size_t)b * 3 * HW + hw;
    v[0] = 10.f*SSC*im[0]; v[1] = 10.f*SSC*im[HW]; v[2] = 10.f*SSC*im[2*HW];
    v[3] = src * e0 * inv; v[4] = src * e1 * inv; v[5] = src * e2 * inv;
}

__global__ void __launch_bounds__(NTHR, 1) fused_kernel(
    const float* __restrict__ logit, const int* __restrict__ target,
    const float* __restrict__ image, const float* __restrict__ srcmap,
    const float* __restrict__ dstmap, float* __restrict__ out)
{
    __shared__ float    red[NTHR/32];
    __shared__ unsigned s_fi[NTHR/32][2][KK+1];  // double-buffered {fi,fi}
    __shared__ unsigned s_fj[NTHR/32][2][12];    // double-buffered fj pairs
    const int tid  = threadIdx.x;
    const int lane = tid & 31;
    const int wid  = tid >> 5;

    // ============ Phase 1a: per-pixel softmax, CE, centers, compaction ======
    {
        int t = blockIdx.x * NTHR + tid;
        float ce = 0.f;
        bool active = false;

        if (t < NPIX) {
            int b  = t / HW;
            int hw = t - b * HW;

            const float* lg = logit + (size_t)b * 3 * HW + hw;
            float l0 = lg[0], l1 = lg[HW], l2 = lg[2*HW];
            float m  = fmaxf(l0, fmaxf(l1, l2));
            float e0 = expf(l0 - m), e1 = expf(l1 - m), e2 = expf(l2 - m);
            float s  = e0 + e1 + e2;
            float inv = 1.f / s;

            int   tg  = target[t];
            float lt  = (tg == 0) ? l0 : ((tg == 1) ? l1 : l2);
            float dst = dstmap[t];
            ce = -((lt - m) - logf(s)) * dst;

            const float* im = image + (size_t)b * 3 * HW + hw;
            g_crgb[t] = make_float4(SSC*im[0], SSC*im[HW], SSC*im[2*HW], 0.f);
            g_cw[t]   = make_float4(e0*inv, e1*inv, e2*inv, 0.f);

            active = (dst == 0.0f);
        }

        unsigned mask = __ballot_sync(0xffffffffu, active);
        if (mask) {
            int leader = __ffs(mask) - 1;
            int base   = 0;
            if (lane == leader) base = atomicAdd(&g_count, __popc(mask));
            base = __shfl_sync(0xffffffffu, base, leader);
            if (active) g_list[base + __popc(mask & ((1u << lane) - 1))] = t;
        }

        #pragma unroll
        for (int s2 = 16; s2 > 0; s2 >>= 1)
            ce += __shfl_xor_sync(0xffffffffu, ce, s2);
        if (lane == 0) red[wid] = ce;
        __syncthreads();
        if (wid == 0) {
            float v = (lane < NTHR/32) ? red[lane] : 0.f;
            #pragma unroll
            for (int s2 = 8; s2 > 0; s2 >>= 1)
                v += __shfl_xor_sync(0xffffffffu, v, s2);
            if (lane == 0) atomicAdd(&g_ce, (double)v);
        }
    }

    // ============ Phase 1b: channel-paired staging (both parity copies) =====
    {
        int tt = blockIdx.x * NTHR + tid;
        if (tt < NTASK) {
            int m   = tt % 81 + 5;        // pair index 5..85
            int r2  = tt / 81;
            int row = r2 % Hh + SPAN;     // padded row 11..170
            int r3  = r2 / Hh;            // 0..3
            int b   = r3 & 1;
            int p   = r3 >> 1;            // parity copy
            int c0  = 2*m + p;            // padded cols (c0, c0+1)

            float A[6], B[6];
            loadcol(logit, image, srcmap, b, row, c0,     A);
            loadcol(logit, image, srcmap, b, row, c0 + 1, B);

            uint4 o1; uint2 o2;
            o1.x = h2u(__floats2half2_rn(A[0], B[0]));   // r pair
            o1.y = h2u(__floats2half2_rn(A[1], B[1]));   // g pair
            o1.z = h2u(__floats2half2_rn(A[2], B[2]));   // b pair
            o1.w = h2u(__floats2half2_rn(A[3], B[3]));   // sy0 pair
            o2.x = h2u(__floats2half2_rn(A[4], B[4]));   // sy1 pair
            o2.y = h2u(__floats2half2_rn(A[5], B[5]));   // sy2 pair
            int idx = ((p * Bz + b) * PH + row) * PPW + m;
            g_P1[idx] = o1;
            g_P2[idx] = o2;
        }
    }

    // ================= Grid barrier =========================================
    __syncthreads();
    if (tid == 0) {
        __threadfence();
        atomicAdd(&g_bar1, 1u);
        while (*(volatile unsigned*)&g_bar1 < NBLK) { __nanosleep(32); }
        __threadfence();
    }
    __syncthreads();

    // ========== Phase 2: warp-per-pixel, 2 offsets/lane, half2 math =========
    {
        const int count = *(volatile int*)&g_count;
        const int gw    = blockIdx.x * (NTHR/32) + wid;
        float facc = 0.f;

        // pixel-invariant per-lane descriptors (hoisted out of the px loop)
        int      pidx[9];    // record index di*PPW+q
        unsigned pmsk[9];    // lane-pair validity mask
        int      pdq[9];     // di | (q<<5)  (for fifj build)
        #pragma unroll
        for (int it = 0; it < 9; it++) {
            int s = it*32 + lane;
            bool valid = (s < 276);               // 23 rows x 12 pairs
            int sc = valid ? s : 0;
            int di = (sc * 2731) >> 15;           // sc/12
            int q  = sc - di * 12;
            pidx[it] = di * PPW + q;
            pmsk[it] = valid ? ((q == 11) ? 0x0000FFFFu : 0xFFFFFFFFu) : 0u;
            pdq[it]  = di | (q << 5);
        }

        int nb = 0;                              // table buffer selector
        int tcur = (gw < count) ? g_list[gw] : 0; // warp-uniform broadcast load

        for (int px = gw; px < count; px += NWARPS) {
            int t = tcur;
            int pxn = px + NWARPS;
            if (pxn < count) tcur = g_list[pxn];  // prefetch next pixel id

            int b  = t / HW;
            int hw = t - b * HW;
            int i  = hw / Ww;
            int j  = hw - i * Ww;

            // issue center loads early (overlap with table build)
            float4 cr = g_crgb[t];
            float4 cy = g_cw[t];

            // per-pixel spatial tables (warp-cooperative fp32 MUFU),
            // double-buffered so no trailing syncwarp is needed
            if (lane < KK) {
                float xi = (float)(5*i - lane + SPAN) * (1.f/6.f);
                s_fi[wid][nb][lane] = h2u(__float2half2_rn(ex2f(xi*xi*C1)));
            }
            if (lane < 12) {
                int djA = 2*lane;
                float xa = (float)(5*j - djA     + SPAN) * (1.f/6.f);
                float xb = (float)(5*j - djA - 1 + SPAN) * (1.f/6.f);
                s_fj[wid][nb][lane] = h2u(__floats2half2_rn(ex2f(xa*xa*C1), ex2f(xb*xb*C1)));
            }
            __syncwarp();                         // write -> read ordering

            // fold spatial product per lane-slot: fifj = fi[di]*fj[q]
            __half2 fifj[9];
            #pragma unroll
            for (int it = 0; it < 9; it++) {
                int di = pdq[it] & 31, q = pdq[it] >> 5;
                fifj[it] = __hmul2(u2h(s_fi[wid][nb][di]), u2h(s_fj[wid][nb][q]));
            }
            nb ^= 1;                              // next pixel writes other buf

            __half2 crr = __float2half2_rn(cr.x);
            __half2 cgg = __float2half2_rn(cr.y);
            __half2 cbb = __float2half2_rn(cr.z);
            __half2 w0  = __float2half2_rn(1.f - cy.x);
            __half2 w1  = __float2half2_rn(1.f - cy.y);
            __half2 w2  = __float2half2_rn(1.f - cy.z);
            int wbase = (((j & 1) * Bz + b) * PH + i) * PPW + (j >> 1);
            const uint4* B1 = g_P1 + wbase;
            const uint2* B2 = g_P2 + wbase;

            __half2 acc2 = u2h(0u);
            #pragma unroll
            for (int it = 0; it < 9; it++) {
                uint4 v1 = __ldg(B1 + pidx[it]);   // {r,g,b,sy0} pairs (16B)
                uint2 v2 = __ldg(B2 + pidx[it]);   // {sy1,sy2} pairs (8B)
                __half2 dr = __hsub2(crr, u2h(v1.x));
                __half2 dg = __hsub2(cgg, u2h(v1.y));
                __half2 db = __hsub2(cbb, u2h(v1.z));
                __half2 ss = __hfma2(dr, dr, __hfma2(dg, dg, __hmul2(db, db)));
                __half2 krgb = hex2(__hneg2(ss));       // exp(-0.5*||d||^2) x2
                __half2 km = h2and(__hadd2(krgb, fifj[it]), pmsk[it]);
                __half2 sn = __hmul2(u2h(v1.w), w0);    // sum_c sy_c*(1-y_pc)
                sn = __hfma2(u2h(v2.x), w1, sn);
                sn = __hfma2(u2h(v2.y), w2, sn);
                acc2 = __hfma2(km, sn, acc2);
            }
            float2 fa = __half22float2(acc2);
            facc += fa.x + fa.y;
        }

        #pragma unroll
        for (int s2 = 16; s2 > 0; s2 >>= 1)
            facc += __shfl_xor_sync(0xffffffffu, facc, s2);
        __syncthreads();
        if (lane == 0) red[wid] = facc;
        __syncthreads();
        if (wid == 0) {
            float v = (lane < NTHR/32) ? red[lane] : 0.f;
            #pragma unroll
            for (int s2 = 8; s2 > 0; s2 >>= 1)
                v += __shfl_xor_sync(0xffffffffu, v, s2);
            if (lane == 0) atomicAdd(&g_gcrf, (double)v);
        }
    }

    // ================= Fin: last block writes + resets ======================
    __syncthreads();
    if (tid == 0) {
        __threadfence();
        unsigned d = atomicAdd(&g_done, 1u);
        if (d == NBLK - 1) {
            __threadfence();
            out[0] = (float)((g_ce + 0.15 * g_gcrf) / (double)NPIX);
            g_ce = 0.0; g_gcrf = 0.0;
            g_count = 0; g_bar1 = 0; g_done = 0;
        }
    }
}

extern "C" void kernel_launch(void* const* d_in, const int* in_sizes, int n_in,
                              void* d_out, int out_size)
{
    const float* logit  = (const float*)d_in[0];
    const int*   target = (const int*)  d_in[1];
    const float* image  = (const float*)d_in[2];
    const float* srcmap = (const float*)d_in[3];
    const float* dstmap = (const float*)d_in[4];
    float* out = (float*)d_out;

    fused_kernel<<<NBLK, NTHR>>>(logit, target, image, srcmap, dstmap, out);
}